// round 3
// baseline (speedup 1.0000x reference)
#include <cuda_runtime.h>
#include <math.h>

#define BATCH      8
#define NPTS       16384
#define ROWS       (BATCH * NPTS)       // 131072
#define FIELD      512
#define OUT_DIM    515
#define TOPK       1024

__device__ float g_H[(size_t)ROWS * FIELD];
__device__ float g_E[(size_t)ROWS * OUT_DIM];
__device__ float g_imp[ROWS];
__device__ int   g_top[BATCH * TOPK];

// XLA/CHLO f32 erf: clamp [-4,4], kAlpha/kBeta rational, division.
__device__ __forceinline__ float xla_erf_f32(float x)
{
    x = fminf(fmaxf(x, -4.0f), 4.0f);
    const float z = __fmul_rn(x, x);
    float p = fmaf(z, -2.72614225801306e-10f, 2.77068142495902e-08f);
    p = fmaf(z, p, -2.10102402082508e-06f);
    p = fmaf(z, p, -5.69250639462346e-05f);
    p = fmaf(z, p, -7.34990630326855e-04f);
    p = fmaf(z, p, -2.95459980854025e-03f);
    p = fmaf(z, p, -1.60960333262415e-02f);
    p = __fmul_rn(x, p);
    float q = fmaf(z, -1.45660718464996e-05f, -2.13374055278905e-04f);
    q = fmaf(z, q, -1.68282697438203e-03f);
    q = fmaf(z, q, -7.37332916720468e-03f);
    q = fmaf(z, q, -1.42647390514189e-02f);
    return __fdiv_rn(p, q);
}

// jax.nn.gelu exact: x * (erf(x / sqrt(2)) + 1) / 2, division form.
__device__ __forceinline__ float xla_gelu(float v)
{
    const float t = __fdiv_rn(v, 1.4142135623730951f);
    const float s = __fadd_rn(xla_erf_f32(t), 1.0f);
    return __fmul_rn(__fmul_rn(v, s), 0.5f);
}

#define BM 128
#define BN 64
#define BK 16
#define TM 8
#define TN 4

__global__ __launch_bounds__(256) void gemm1_gelu_kernel(
    const float* __restrict__ coords,
    const float* __restrict__ dens,
    const float* __restrict__ W1,
    const float* __restrict__ b1)
{
    __shared__ float As[BK][BM + 4];
    __shared__ float Bs[BK][BN + 4];

    const int col0 = blockIdx.x * BN;
    const int row0 = blockIdx.y * BM;
    const int tid  = threadIdx.x;
    const int trow = tid >> 4;
    const int tcol = tid & 15;

    // coords (k = 0, 1) seed the ascending-k FMA chain.
    float acc[TM][TN];
#pragma unroll
    for (int i = 0; i < TM; i++) {
        const size_t r  = (size_t)row0 + trow * TM + i;
        const float  c0 = coords[r * 2 + 0];
        const float  c1 = coords[r * 2 + 1];
#pragma unroll
        for (int j = 0; j < TN; j++) {
            const int n = col0 + tcol * TN + j;
            float a = fmaf(c0, W1[n], 0.0f);
            a = fmaf(c1, W1[FIELD + n], a);
            acc[i][j] = a;
        }
    }

    for (int k0 = 0; k0 < FIELD; k0 += BK) {
#pragma unroll
        for (int s = tid; s < (BM * BK / 4); s += 256) {
            int r = s >> 2;
            int v = s & 3;
            const float4 a = *reinterpret_cast<const float4*>(
                &dens[(size_t)(row0 + r) * FIELD + k0 + v * 4]);
            As[v * 4 + 0][r] = a.x;
            As[v * 4 + 1][r] = a.y;
            As[v * 4 + 2][r] = a.z;
            As[v * 4 + 3][r] = a.w;
        }
        {
            int kk = tid >> 4;
            int nn = (tid & 15) * 4;
            const float4 bv = *reinterpret_cast<const float4*>(
                &W1[(size_t)(2 + k0 + kk) * FIELD + col0 + nn]);
            Bs[kk][nn + 0] = bv.x;
            Bs[kk][nn + 1] = bv.y;
            Bs[kk][nn + 2] = bv.z;
            Bs[kk][nn + 3] = bv.w;
        }
        __syncthreads();

#pragma unroll
        for (int kk = 0; kk < BK; kk++) {
            float a[TM], b[TN];
#pragma unroll
            for (int i = 0; i < TM; i++) a[i] = As[kk][trow * TM + i];
#pragma unroll
            for (int j = 0; j < TN; j++) b[j] = Bs[kk][tcol * TN + j];
#pragma unroll
            for (int i = 0; i < TM; i++)
#pragma unroll
                for (int j = 0; j < TN; j++)
                    acc[i][j] = fmaf(a[i], b[j], acc[i][j]);
        }
        __syncthreads();
    }

#pragma unroll
    for (int i = 0; i < TM; i++) {
        const size_t r = (size_t)row0 + trow * TM + i;
#pragma unroll
        for (int j = 0; j < TN; j++) {
            const int n = col0 + tcol * TN + j;
            const float v = __fadd_rn(acc[i][j], b1[n]);
            g_H[r * FIELD + n] = xla_gelu(v);
        }
    }
}

__global__ __launch_bounds__(256) void gemm2_kernel(
    const float* __restrict__ W2,
    const float* __restrict__ b2)
{
    __shared__ float As[BK][BM + 4];
    __shared__ float Bs[BK][BN + 4];

    const int col0 = blockIdx.x * BN;
    const int row0 = blockIdx.y * BM;
    const int tid  = threadIdx.x;
    const int trow = tid >> 4;
    const int tcol = tid & 15;

    float acc[TM][TN];
#pragma unroll
    for (int i = 0; i < TM; i++)
#pragma unroll
        for (int j = 0; j < TN; j++) acc[i][j] = 0.0f;

    for (int k0 = 0; k0 < FIELD; k0 += BK) {
#pragma unroll
        for (int s = tid; s < (BM * BK / 4); s += 256) {
            int r = s >> 2;
            int v = s & 3;
            const float4 a = *reinterpret_cast<const float4*>(
                &g_H[(size_t)(row0 + r) * FIELD + k0 + v * 4]);
            As[v * 4 + 0][r] = a.x;
            As[v * 4 + 1][r] = a.y;
            As[v * 4 + 2][r] = a.z;
            As[v * 4 + 3][r] = a.w;
        }
        {
            int kk = tid >> 4;
            int nn = (tid & 15) * 4;
#pragma unroll
            for (int q = 0; q < 4; q++) {
                int n = col0 + nn + q;
                Bs[kk][nn + q] =
                    (n < OUT_DIM) ? W2[(size_t)(k0 + kk) * OUT_DIM + n] : 0.0f;
            }
        }
        __syncthreads();

#pragma unroll
        for (int kk = 0; kk < BK; kk++) {
            float a[TM], b[TN];
#pragma unroll
            for (int i = 0; i < TM; i++) a[i] = As[kk][trow * TM + i];
#pragma unroll
            for (int j = 0; j < TN; j++) b[j] = Bs[kk][tcol * TN + j];
#pragma unroll
            for (int i = 0; i < TM; i++)
#pragma unroll
                for (int j = 0; j < TN; j++)
                    acc[i][j] = fmaf(a[i], b[j], acc[i][j]);
        }
        __syncthreads();
    }

#pragma unroll
    for (int i = 0; i < TM; i++) {
        const size_t r = (size_t)row0 + trow * TM + i;
#pragma unroll
        for (int j = 0; j < TN; j++) {
            const int n = col0 + tcol * TN + j;
            if (n < OUT_DIM)
                g_E[r * OUT_DIM + n] = __fadd_rn(acc[i][j], b2[n]);
        }
    }
}

// XLA:GPU-style row reduction: lane-strided-by-32 FMA accumulate,
// shfl-down tree, correctly-rounded sqrt at lane 0.
__global__ __launch_bounds__(256) void norm_kernel()
{
    const int gwarp = (blockIdx.x * blockDim.x + threadIdx.x) >> 5;
    const int lane  = threadIdx.x & 31;
    if (gwarp >= ROWS) return;

    const float* src = g_E + (size_t)gwarp * OUT_DIM;
    float s = 0.0f;
    for (int c = lane; c < OUT_DIM; c += 32) {
        const float v = src[c];
        s = fmaf(v, v, s);
    }
#pragma unroll
    for (int o = 16; o; o >>= 1)
        s = __fadd_rn(s, __shfl_down_sync(0xffffffffu, s, o));
    if (lane == 0) g_imp[gwarp] = __fsqrt_rn(s);
}

__global__ __launch_bounds__(1024) void topk_kernel()
{
    extern __shared__ float smem[];
    float* key = smem;
    int*   idx = (int*)(smem + NPTS);

    const int b = blockIdx.x;
    for (int i = threadIdx.x; i < NPTS; i += blockDim.x) {
        key[i] = g_imp[(size_t)b * NPTS + i];
        idx[i] = i;
    }
    __syncthreads();

    for (int k = 2; k <= NPTS; k <<= 1) {
        for (int j = k >> 1; j > 0; j >>= 1) {
            for (int i = threadIdx.x; i < NPTS; i += blockDim.x) {
                const int ixj = i ^ j;
                if (ixj > i) {
                    const bool dirAsc = ((i & k) == 0);
                    float k1 = key[i], k2 = key[ixj];
                    int   i1 = idx[i], i2 = idx[ixj];
                    bool partnerBefore = (k2 > k1) || (k2 == k1 && i2 < i1);
                    if (partnerBefore == dirAsc) {
                        key[i] = k2; key[ixj] = k1;
                        idx[i] = i2; idx[ixj] = i1;
                    }
                }
            }
            __syncthreads();
        }
    }

    for (int t = threadIdx.x; t < TOPK; t += blockDim.x)
        g_top[b * TOPK + t] = idx[t];
}

__global__ __launch_bounds__(128) void gather_kernel(float* __restrict__ out)
{
    const int slot = blockIdx.x;
    const int b    = slot >> 10;
    const int src  = g_top[slot];
    const float* row = g_E + ((size_t)b * NPTS + src) * OUT_DIM;

    float* pos = out;
    float* st  = out + (size_t)BATCH * TOPK * 2;
    float* wt  = st  + (size_t)BATCH * TOPK * FIELD;

    for (int c = threadIdx.x; c < OUT_DIM; c += blockDim.x) {
        const float v = row[c];
        if (c < 2)                pos[(size_t)slot * 2 + c]          = v;
        else if (c < 2 + FIELD)   st[(size_t)slot * FIELD + (c - 2)] = v;
        else                      wt[slot]                           = v;
    }
}

extern "C" void kernel_launch(void* const* d_in, const int* in_sizes, int n_in,
                              void* d_out, int out_size)
{
    const float* coords = (const float*)d_in[0];
    const float* dens   = (const float*)d_in[1];
    const float* W1     = (const float*)d_in[2];
    const float* b1     = (const float*)d_in[3];
    const float* W2     = (const float*)d_in[4];
    const float* b2     = (const float*)d_in[5];
    float* out = (float*)d_out;

    gemm1_gelu_kernel<<<dim3(FIELD / BN, ROWS / BM), 256>>>(coords, dens, W1, b1);
    gemm2_kernel<<<dim3((OUT_DIM + BN - 1) / BN, ROWS / BM), 256>>>(W2, b2);
    norm_kernel<<<ROWS / 8, 256>>>();

    cudaFuncSetAttribute(topk_kernel,
                         cudaFuncAttributeMaxDynamicSharedMemorySize,
                         NPTS * (sizeof(float) + sizeof(int)));
    topk_kernel<<<BATCH, 1024, NPTS * (sizeof(float) + sizeof(int))>>>();

    gather_kernel<<<BATCH * TOPK, 128>>>(out);
}